// round 16
// baseline (speedup 1.0000x reference)
#include <cuda_runtime.h>
#include <cstdint>
#include <cstddef>

#define T_STEPS 2048
#define BATCH   64
#define IN_DIM  256
#define HID     512
#define BH      (BATCH * HID)

__device__ __align__(128) float g_xproj[(size_t)T_STEPS * BH]; // 256 MiB

typedef unsigned long long ull;

__device__ __forceinline__ ull fma2_(ull a, ull b, ull c) {
    ull d;
    asm("fma.rn.f32x2 %0, %1, %2, %3;" : "=l"(d) : "l"(a), "l"(b), "l"(c));
    return d;
}
__device__ __forceinline__ ull pack2_(float x) {
    ull d;
    asm("mov.b64 %0, {%1, %1};" : "=l"(d) : "r"(__float_as_int(x)));
    return d;
}
__device__ __forceinline__ ull packab_(float lo, float hi) {
    ull d;
    asm("mov.b64 %0, {%1, %2};" : "=l"(d)
        : "r"(__float_as_int(lo)), "r"(__float_as_int(hi)));
    return d;
}

// ------ Phase A: x_proj GEMM, 128x128x16 (R15, measured-equal) --------------
#define XBM 128
#define XBN 128
#define XBK 16

__global__ __launch_bounds__(256) void xproj_gemm_kernel(
    const float* __restrict__ A, const float* __restrict__ B)
{
    __shared__ float As[XBK][XBM];
    __shared__ float Bs[XBK][XBN];

    const int tid = threadIdx.x;
    const int tx = tid % 16;
    const int ty = tid / 16;
    const size_t mBase = (size_t)blockIdx.y * XBM;
    const int    nBase = blockIdx.x * XBN;

    ull acc[8][4];
#pragma unroll
    for (int i = 0; i < 8; i++)
#pragma unroll
        for (int j = 0; j < 4; j++) acc[i][j] = 0ull;

    for (int kt = 0; kt < IN_DIM; kt += XBK) {
#pragma unroll
        for (int s = 0; s < 2; s++) {
            int row = (tid >> 2) + s * 64;
            int k4  = (tid & 3) * 4;
            float4 v = *(const float4*)&A[(mBase + row) * IN_DIM + kt + k4];
            As[k4 + 0][row] = v.x; As[k4 + 1][row] = v.y;
            As[k4 + 2][row] = v.z; As[k4 + 3][row] = v.w;
        }
        {
            int row = tid >> 4;
            int n8  = (tid & 15) * 8;
            const float4* src = (const float4*)&B[(size_t)(kt + row) * HID + nBase + n8];
            *(float4*)&Bs[row][n8]     = src[0];
            *(float4*)&Bs[row][n8 + 4] = src[1];
        }
        __syncthreads();

#pragma unroll
        for (int k = 0; k < XBK; k++) {
            float a[8];
            *(float4*)&a[0] = *(const float4*)&As[k][ty * 8];
            *(float4*)&a[4] = *(const float4*)&As[k][ty * 8 + 4];
            ulonglong2 b0 = *(const ulonglong2*)&Bs[k][tx * 8];
            ulonglong2 b1 = *(const ulonglong2*)&Bs[k][tx * 8 + 4];
#pragma unroll
            for (int i = 0; i < 8; i++) {
                ull ap = pack2_(a[i]);
                acc[i][0] = fma2_(ap, b0.x, acc[i][0]);
                acc[i][1] = fma2_(ap, b0.y, acc[i][1]);
                acc[i][2] = fma2_(ap, b1.x, acc[i][2]);
                acc[i][3] = fma2_(ap, b1.y, acc[i][3]);
            }
        }
        __syncthreads();
    }

#pragma unroll
    for (int i = 0; i < 8; i++) {
        size_t row = mBase + ty * 8 + i;
        float* dst = &g_xproj[row * HID + nBase + tx * 8];
        float2 p0 = *(float2*)&acc[i][0];
        float2 p1 = *(float2*)&acc[i][1];
        float2 p2 = *(float2*)&acc[i][2];
        float2 p3 = *(float2*)&acc[i][3];
        *(float4*)dst       = make_float4(p0.x, p0.y, p1.x, p1.y);
        *(float4*)(dst + 4) = make_float4(p2.x, p2.y, p3.x, p3.y);
    }
}

// ------ Phase B: R14 scan + b64-packed sends (halve DSMEM message count) ----
#define CLS  8
#define BPC  4
#define JPC  64
#define NKC  16
#define KC   (HID / NKC)      // 32
#define HPAD 516

#define HS_OFF   0
#define HS_FLOATS (2 * BPC * HPAD)            // 4128
#define RED_OFF  (HS_OFF + HS_FLOATS)
#define RED_PHASE (NKC * 256)                 // 4096 floats
#define RED_FLOATS (2 * RED_PHASE)
#define MB_OFF   (RED_OFF + RED_FLOATS)       // [2][8] u64 mbars
#define SCAN_SMEM_BYTES  ((MB_OFF + 32) * 4)  // ~49.4 KB

#define TX_PER_RANK (256 * 4)                 // 1024 B per source rank/phase

__device__ __forceinline__ void cluster_sync_() {
    asm volatile("barrier.cluster.arrive.aligned;" ::: "memory");
    asm volatile("barrier.cluster.wait.aligned;"   ::: "memory");
}
__device__ __forceinline__ void mbar_init_(unsigned a, unsigned cnt) {
    asm volatile("mbarrier.init.shared.b64 [%0], %1;" :: "r"(a), "r"(cnt) : "memory");
}
__device__ __forceinline__ void mbar_expect_tx_(unsigned a, unsigned bytes) {
    asm volatile("mbarrier.arrive.expect_tx.shared.b64 _, [%0], %1;"
                 :: "r"(a), "r"(bytes) : "memory");
}
__device__ __forceinline__ void mbar_wait_(unsigned a, unsigned parity) {
    unsigned done;
    asm volatile(
        "{\n\t.reg .pred p;\n\t"
        "mbarrier.try_wait.parity.acquire.cta.shared::cta.b64 p, [%1], %2;\n\t"
        "selp.b32 %0, 1, 0, p;\n\t}"
        : "=r"(done) : "r"(a), "r"(parity) : "memory");
    if (!done) {
        asm volatile(
            "{\n\t.reg .pred P1;\n\t"
            "WL_%=:\n\t"
            "mbarrier.try_wait.parity.acquire.cta.shared::cta.b64 P1, [%0], %1, 0x989680;\n\t"
            "@P1 bra.uni WD_%=;\n\t"
            "bra.uni WL_%=;\n\t"
            "WD_%=:\n\t}"
            :: "r"(a), "r"(parity) : "memory");
    }
}
__device__ __forceinline__ void st_async_u64_(unsigned raddr, ull v, unsigned rmbar) {
    asm volatile(
        "st.async.shared::cluster.mbarrier::complete_tx::bytes.b64 [%0], %1, [%2];"
        :: "r"(raddr), "l"(v), "r"(rmbar) : "memory");
}

__global__ __launch_bounds__(256, 1) __cluster_dims__(CLS, 1, 1)
void rnn_scan_kernel(const float* __restrict__ w_rec,
                     float* __restrict__ out, int write_last)
{
    extern __shared__ float smem[];
    float* hs  = smem + HS_OFF;   // [2][BPC][HPAD]
    float* red = smem + RED_OFF;  // [2][NKC][256]

    const int tid  = threadIdx.x;
    const int wrp  = tid >> 5;    // warp id 0..7 == source rank it consumes
    const int rank = blockIdx.x & (CLS - 1);
    const int b0   = (blockIdx.x >> 3) * BPC;
    const int j0   = rank * JPC;

    const int kc = tid >> 4;      // 0..15 k-chunk
    const int jg = tid & 15;      // 0..15 j-group (4 cols)
    const int ob = tid >> 6;      // 0..3  output batch
    const int oj = tid & 63;      // 0..63 output column

    // ---- prologue: h zero, mbars, w slice -> registers ----
    for (int i = tid; i < HS_FLOATS; i += 256) hs[i] = 0.0f;
    if (tid == 0) {
        unsigned mb = (unsigned)__cvta_generic_to_shared(smem + MB_OFF);
#pragma unroll
        for (int m = 0; m < 2 * CLS; m++)
            mbar_init_(mb + m * 8, 1);
    }

    // w_[ki][cp] = w_rec[kc*32+ki][j0+jg*4 .. +3]  (64 ull regs)
    ull w_[KC][2];
#pragma unroll
    for (int ki = 0; ki < KC; ki++) {
        float4 wv = *(const float4*)&w_rec[(size_t)(kc * KC + ki) * HID + j0 + jg * 4];
        w_[ki][0] = packab_(wv.x, wv.y);
        w_[ki][1] = packab_(wv.z, wv.w);
    }

    __syncthreads();
    cluster_sync_();   // peers' smem + mbarriers live before any st.async

    const unsigned hs_loc = (unsigned)__cvta_generic_to_shared(hs);
    const unsigned mb_loc = (unsigned)__cvta_generic_to_shared(smem + MB_OFF);
    unsigned peer_hs[CLS], peer_mb[CLS];
#pragma unroll
    for (int r = 0; r < CLS; r++) {
        asm("mapa.shared::cluster.u32 %0, %1, %2;" : "=r"(peer_hs[r]) : "r"(hs_loc), "r"(r));
        asm("mapa.shared::cluster.u32 %0, %1, %2;" : "=r"(peer_mb[r]) : "r"(mb_loc), "r"(r));
    }

    const size_t xbase = (size_t)(b0 + ob) * HID + j0 + oj;
    // b64 send: pair (oj&~1, oj|1); even lanes send
    const unsigned st_off_base = (unsigned)((ob * HPAD + j0 + (oj & ~1)) * 4);
    const unsigned my_mb_off  = (unsigned)(wrp * 8);
    const unsigned snd_mb_off = (unsigned)(rank * 8);

    int par0 = 0, par1 = 0;

#pragma unroll 1
    for (int t = 0; t < T_STEPS; t++) {
        const int q  = t & 1;
        const int qn = q ^ 1;

        float xv = __ldg(&g_xproj[(size_t)t * BH + xbase]);

        // wait ONLY for our source rank's 1KB block
        if (t > 0) {
            if (q == 0) { mbar_wait_(mb_loc + my_mb_off,           par0); par0 ^= 1; }
            else        { mbar_wait_(mb_loc + CLS * 8 + my_mb_off, par1); par1 ^= 1; }
        }
        if (tid == 0 && t < T_STEPS - 1) {
            unsigned base = mb_loc + (unsigned)qn * (CLS * 8);
#pragma unroll
            for (int r = 0; r < CLS; r++)
                mbar_expect_tx_(base + r * 8, TX_PER_RANK);
        }

        // ---- split-K partials: w in registers, h broadcast from smem ----
        const float* hp = hs + q * BPC * HPAD + kc * KC;
        float* redq = red + q * RED_PHASE;

        ull acc2[BPC][2];
#pragma unroll
        for (int b = 0; b < BPC; b++) { acc2[b][0] = 0ull; acc2[b][1] = 0ull; }

#pragma unroll
        for (int ki = 0; ki < KC; ki += 4) {
#pragma unroll
            for (int b = 0; b < BPC; b++) {
                float4 h4 = *(const float4*)(hp + b * HPAD + ki);
                ull hh;
                hh = pack2_(h4.x);
                acc2[b][0] = fma2_(hh, w_[ki + 0][0], acc2[b][0]);
                acc2[b][1] = fma2_(hh, w_[ki + 0][1], acc2[b][1]);
                hh = pack2_(h4.y);
                acc2[b][0] = fma2_(hh, w_[ki + 1][0], acc2[b][0]);
                acc2[b][1] = fma2_(hh, w_[ki + 1][1], acc2[b][1]);
                hh = pack2_(h4.z);
                acc2[b][0] = fma2_(hh, w_[ki + 2][0], acc2[b][0]);
                acc2[b][1] = fma2_(hh, w_[ki + 2][1], acc2[b][1]);
                hh = pack2_(h4.w);
                acc2[b][0] = fma2_(hh, w_[ki + 3][0], acc2[b][0]);
                acc2[b][1] = fma2_(hh, w_[ki + 3][1], acc2[b][1]);
            }
        }

#pragma unroll
        for (int b = 0; b < BPC; b++) {
            float2 p0 = *(float2*)&acc2[b][0];
            float2 p1 = *(float2*)&acc2[b][1];
            *(float4*)&redq[kc * 256 + b * 64 + jg * 4] =
                make_float4(p0.x, p0.y, p1.x, p1.y);
        }
        __syncthreads();

        // ---- reduce over 16 k-chunks (two ILP chains), activate ----
        float s0 = 0.0f, s1 = 0.0f;
#pragma unroll
        for (int c = 0; c < NKC; c += 2) {
            s0 += redq[(c + 0) * 256 + tid];
            s1 += redq[(c + 1) * 256 + tid];
        }
        float hn = tanhf(xv + (s0 + s1));

        // ---- broadcast h_{t+1}: b64 pairs, even lanes send ----
        if (t < T_STEPS - 1) {
            float hp2 = __shfl_xor_sync(0xffffffffu, hn, 1);
            if ((tid & 1) == 0) {
                ull pkt = packab_(hn, hp2);
                unsigned doff = (unsigned)(qn * BPC * HPAD * 4) + st_off_base;
                unsigned moff = (unsigned)qn * (CLS * 8) + snd_mb_off;
#pragma unroll
                for (int r = 0; r < CLS; r++)
                    st_async_u64_(peer_hs[r] + doff, pkt, peer_mb[r] + moff);
            }
        }

        out[(size_t)t * BH + xbase] = hn;
        if (write_last && t == T_STEPS - 1)
            out[(size_t)T_STEPS * BH + xbase] = hn;
    }
    cluster_sync_();
}

// ---------------- launch ----------------------------------------------------
extern "C" void kernel_launch(void* const* d_in, const int* in_sizes, int n_in,
                              void* d_out, int out_size)
{
    const float* input = (const float*)d_in[0];
    const float* w_in  = (const float*)d_in[1];
    const float* w_rec = (const float*)d_in[2];
    float* out = (float*)d_out;

    int write_last =
        ((size_t)out_size >= (size_t)T_STEPS * BH + (size_t)BH) ? 1 : 0;

    cudaFuncSetAttribute(rnn_scan_kernel,
                         cudaFuncAttributeMaxDynamicSharedMemorySize,
                         SCAN_SMEM_BYTES);

    dim3 grid(HID / XBN, (T_STEPS * BATCH) / XBM);   // (4, 1024)
    xproj_gemm_kernel<<<grid, 256>>>(input, w_in);

    rnn_scan_kernel<<<BATCH / BPC * CLS, 256, SCAN_SMEM_BYTES>>>(
        w_rec, out, write_last);
}

// round 17
// speedup vs baseline: 1.0402x; 1.0402x over previous
#include <cuda_runtime.h>
#include <cstdint>
#include <cstddef>

#define T_STEPS 2048
#define BATCH   64
#define IN_DIM  256
#define HID     512
#define BH      (BATCH * HID)

__device__ __align__(128) float g_xproj[(size_t)T_STEPS * BH]; // 256 MiB

typedef unsigned long long ull;

__device__ __forceinline__ ull fma2_(ull a, ull b, ull c) {
    ull d;
    asm("fma.rn.f32x2 %0, %1, %2, %3;" : "=l"(d) : "l"(a), "l"(b), "l"(c));
    return d;
}
__device__ __forceinline__ ull pack2_(float x) {
    ull d;
    asm("mov.b64 %0, {%1, %1};" : "=l"(d) : "r"(__float_as_int(x)));
    return d;
}
__device__ __forceinline__ ull packab_(float lo, float hi) {
    ull d;
    asm("mov.b64 %0, {%1, %2};" : "=l"(d)
        : "r"(__float_as_int(lo)), "r"(__float_as_int(hi)));
    return d;
}

// ------ Phase A: x_proj GEMM, 128x128x16 ------------------------------------
#define XBM 128
#define XBN 128
#define XBK 16

__global__ __launch_bounds__(256) void xproj_gemm_kernel(
    const float* __restrict__ A, const float* __restrict__ B)
{
    __shared__ float As[XBK][XBM];
    __shared__ float Bs[XBK][XBN];

    const int tid = threadIdx.x;
    const int tx = tid % 16;
    const int ty = tid / 16;
    const size_t mBase = (size_t)blockIdx.y * XBM;
    const int    nBase = blockIdx.x * XBN;

    ull acc[8][4];
#pragma unroll
    for (int i = 0; i < 8; i++)
#pragma unroll
        for (int j = 0; j < 4; j++) acc[i][j] = 0ull;

    for (int kt = 0; kt < IN_DIM; kt += XBK) {
#pragma unroll
        for (int s = 0; s < 2; s++) {
            int row = (tid >> 2) + s * 64;
            int k4  = (tid & 3) * 4;
            float4 v = *(const float4*)&A[(mBase + row) * IN_DIM + kt + k4];
            As[k4 + 0][row] = v.x; As[k4 + 1][row] = v.y;
            As[k4 + 2][row] = v.z; As[k4 + 3][row] = v.w;
        }
        {
            int row = tid >> 4;
            int n8  = (tid & 15) * 8;
            const float4* src = (const float4*)&B[(size_t)(kt + row) * HID + nBase + n8];
            *(float4*)&Bs[row][n8]     = src[0];
            *(float4*)&Bs[row][n8 + 4] = src[1];
        }
        __syncthreads();

#pragma unroll
        for (int k = 0; k < XBK; k++) {
            float a[8];
            *(float4*)&a[0] = *(const float4*)&As[k][ty * 8];
            *(float4*)&a[4] = *(const float4*)&As[k][ty * 8 + 4];
            ulonglong2 b0 = *(const ulonglong2*)&Bs[k][tx * 8];
            ulonglong2 b1 = *(const ulonglong2*)&Bs[k][tx * 8 + 4];
#pragma unroll
            for (int i = 0; i < 8; i++) {
                ull ap = pack2_(a[i]);
                acc[i][0] = fma2_(ap, b0.x, acc[i][0]);
                acc[i][1] = fma2_(ap, b0.y, acc[i][1]);
                acc[i][2] = fma2_(ap, b1.x, acc[i][2]);
                acc[i][3] = fma2_(ap, b1.y, acc[i][3]);
            }
        }
        __syncthreads();
    }

#pragma unroll
    for (int i = 0; i < 8; i++) {
        size_t row = mBase + ty * 8 + i;
        float* dst = &g_xproj[row * HID + nBase + tx * 8];
        float2 p0 = *(float2*)&acc[i][0];
        float2 p1 = *(float2*)&acc[i][1];
        float2 p2 = *(float2*)&acc[i][2];
        float2 p3 = *(float2*)&acc[i][3];
        *(float4*)dst       = make_float4(p0.x, p0.y, p1.x, p1.y);
        *(float4*)(dst + 4) = make_float4(p2.x, p2.y, p3.x, p3.y);
    }
}

// ------ Phase B: R14 scan + distributed arming + 4-chain reduce -------------
#define CLS  8
#define BPC  4
#define JPC  64
#define NKC  16
#define KC   (HID / NKC)      // 32
#define HPAD 516

#define HS_OFF   0
#define HS_FLOATS (2 * BPC * HPAD)            // 4128
#define RED_OFF  (HS_OFF + HS_FLOATS)
#define RED_PHASE (NKC * 256)                 // 4096 floats
#define RED_FLOATS (2 * RED_PHASE)
#define MB_OFF   (RED_OFF + RED_FLOATS)       // [2][8] u64 mbars
#define SCAN_SMEM_BYTES  ((MB_OFF + 32) * 4)  // ~49.4 KB

#define TX_PER_RANK (256 * 4)                 // 1024 B per source rank/phase

__device__ __forceinline__ void cluster_sync_() {
    asm volatile("barrier.cluster.arrive.aligned;" ::: "memory");
    asm volatile("barrier.cluster.wait.aligned;"   ::: "memory");
}
__device__ __forceinline__ void mbar_init_(unsigned a, unsigned cnt) {
    asm volatile("mbarrier.init.shared.b64 [%0], %1;" :: "r"(a), "r"(cnt) : "memory");
}
__device__ __forceinline__ void mbar_expect_tx_(unsigned a, unsigned bytes) {
    asm volatile("mbarrier.arrive.expect_tx.shared.b64 _, [%0], %1;"
                 :: "r"(a), "r"(bytes) : "memory");
}
__device__ __forceinline__ void mbar_wait_(unsigned a, unsigned parity) {
    unsigned done;
    asm volatile(
        "{\n\t.reg .pred p;\n\t"
        "mbarrier.try_wait.parity.acquire.cta.shared::cta.b64 p, [%1], %2;\n\t"
        "selp.b32 %0, 1, 0, p;\n\t}"
        : "=r"(done) : "r"(a), "r"(parity) : "memory");
    if (!done) {
        asm volatile(
            "{\n\t.reg .pred P1;\n\t"
            "WL_%=:\n\t"
            "mbarrier.try_wait.parity.acquire.cta.shared::cta.b64 P1, [%0], %1, 0x989680;\n\t"
            "@P1 bra.uni WD_%=;\n\t"
            "bra.uni WL_%=;\n\t"
            "WD_%=:\n\t}"
            :: "r"(a), "r"(parity) : "memory");
    }
}
__device__ __forceinline__ void st_async_f32_(unsigned raddr, float v, unsigned rmbar) {
    asm volatile(
        "st.async.shared::cluster.mbarrier::complete_tx::bytes.b32 [%0], %1, [%2];"
        :: "r"(raddr), "r"(__float_as_int(v)), "r"(rmbar) : "memory");
}

__global__ __launch_bounds__(256, 1) __cluster_dims__(CLS, 1, 1)
void rnn_scan_kernel(const float* __restrict__ w_rec,
                     float* __restrict__ out, int write_last)
{
    extern __shared__ float smem[];
    float* hs  = smem + HS_OFF;   // [2][BPC][HPAD]
    float* red = smem + RED_OFF;  // [2][NKC][256]

    const int tid  = threadIdx.x;
    const int wrp  = tid >> 5;    // warp id 0..7 == source rank it consumes
    const int rank = blockIdx.x & (CLS - 1);
    const int b0   = (blockIdx.x >> 3) * BPC;
    const int j0   = rank * JPC;

    const int kc = tid >> 4;      // 0..15 k-chunk
    const int jg = tid & 15;      // 0..15 j-group (4 cols)
    const int ob = tid >> 6;      // 0..3  output batch
    const int oj = tid & 63;      // 0..63 output column

    // ---- prologue: h zero, mbars, w slice -> registers ----
    for (int i = tid; i < HS_FLOATS; i += 256) hs[i] = 0.0f;
    if (tid == 0) {
        unsigned mb = (unsigned)__cvta_generic_to_shared(smem + MB_OFF);
#pragma unroll
        for (int m = 0; m < 2 * CLS; m++)
            mbar_init_(mb + m * 8, 1);
    }

    // w_[ki][cp] = w_rec[kc*32+ki][j0+jg*4 .. +3]  (64 ull regs)
    ull w_[KC][2];
#pragma unroll
    for (int ki = 0; ki < KC; ki++) {
        float4 wv = *(const float4*)&w_rec[(size_t)(kc * KC + ki) * HID + j0 + jg * 4];
        w_[ki][0] = packab_(wv.x, wv.y);
        w_[ki][1] = packab_(wv.z, wv.w);
    }

    __syncthreads();
    cluster_sync_();   // peers' smem + mbarriers live before any st.async

    const unsigned hs_loc = (unsigned)__cvta_generic_to_shared(hs);
    const unsigned mb_loc = (unsigned)__cvta_generic_to_shared(smem + MB_OFF);
    unsigned peer_hs[CLS], peer_mb[CLS];
#pragma unroll
    for (int r = 0; r < CLS; r++) {
        asm("mapa.shared::cluster.u32 %0, %1, %2;" : "=r"(peer_hs[r]) : "r"(hs_loc), "r"(r));
        asm("mapa.shared::cluster.u32 %0, %1, %2;" : "=r"(peer_mb[r]) : "r"(mb_loc), "r"(r));
    }

    const size_t xbase = (size_t)(b0 + ob) * HID + j0 + oj;
    const unsigned st_off_base = (unsigned)((ob * HPAD + j0 + oj) * 4);
    const unsigned my_mb_off  = (unsigned)(wrp * 8);
    const unsigned snd_mb_off = (unsigned)(rank * 8);
    const bool lane0 = ((tid & 31) == 0);

    int par0 = 0, par1 = 0;

#pragma unroll 1
    for (int t = 0; t < T_STEPS; t++) {
        const int q  = t & 1;
        const int qn = q ^ 1;

        float xv = __ldg(&g_xproj[(size_t)t * BH + xbase]);

        // wait ONLY for our source rank's 1KB block
        if (t > 0) {
            if (q == 0) { mbar_wait_(mb_loc + my_mb_off,           par0); par0 ^= 1; }
            else        { mbar_wait_(mb_loc + CLS * 8 + my_mb_off, par1); par1 ^= 1; }
        }
        // each warp's lane 0 arms ITS OWN next-phase mbar (tx underflow is legal)
        if (lane0 && t < T_STEPS - 1)
            mbar_expect_tx_(mb_loc + (unsigned)qn * (CLS * 8) + my_mb_off,
                            TX_PER_RANK);

        // ---- split-K partials: w in registers, h broadcast from smem ----
        const float* hp = hs + q * BPC * HPAD + kc * KC;
        float* redq = red + q * RED_PHASE;

        ull acc2[BPC][2];
#pragma unroll
        for (int b = 0; b < BPC; b++) { acc2[b][0] = 0ull; acc2[b][1] = 0ull; }

#pragma unroll
        for (int ki = 0; ki < KC; ki += 4) {
#pragma unroll
            for (int b = 0; b < BPC; b++) {
                float4 h4 = *(const float4*)(hp + b * HPAD + ki);
                ull hh;
                hh = pack2_(h4.x);
                acc2[b][0] = fma2_(hh, w_[ki + 0][0], acc2[b][0]);
                acc2[b][1] = fma2_(hh, w_[ki + 0][1], acc2[b][1]);
                hh = pack2_(h4.y);
                acc2[b][0] = fma2_(hh, w_[ki + 1][0], acc2[b][0]);
                acc2[b][1] = fma2_(hh, w_[ki + 1][1], acc2[b][1]);
                hh = pack2_(h4.z);
                acc2[b][0] = fma2_(hh, w_[ki + 2][0], acc2[b][0]);
                acc2[b][1] = fma2_(hh, w_[ki + 2][1], acc2[b][1]);
                hh = pack2_(h4.w);
                acc2[b][0] = fma2_(hh, w_[ki + 3][0], acc2[b][0]);
                acc2[b][1] = fma2_(hh, w_[ki + 3][1], acc2[b][1]);
            }
        }

#pragma unroll
        for (int b = 0; b < BPC; b++) {
            float2 p0 = *(float2*)&acc2[b][0];
            float2 p1 = *(float2*)&acc2[b][1];
            *(float4*)&redq[kc * 256 + b * 64 + jg * 4] =
                make_float4(p0.x, p0.y, p1.x, p1.y);
        }
        __syncthreads();

        // ---- reduce over 16 k-chunks (four ILP chains), activate ----
        float s0 = 0.0f, s1 = 0.0f, s2 = 0.0f, s3 = 0.0f;
#pragma unroll
        for (int c = 0; c < NKC; c += 4) {
            s0 += redq[(c + 0) * 256 + tid];
            s1 += redq[(c + 1) * 256 + tid];
            s2 += redq[(c + 2) * 256 + tid];
            s3 += redq[(c + 3) * 256 + tid];
        }
        float hn = tanhf(xv + ((s0 + s1) + (s2 + s3)));

        // ---- broadcast h_{t+1} (warp-uniform destinations) ----
        if (t < T_STEPS - 1) {
            unsigned doff = (unsigned)(qn * BPC * HPAD * 4) + st_off_base;
            unsigned moff = (unsigned)qn * (CLS * 8) + snd_mb_off;
#pragma unroll
            for (int r = 0; r < CLS; r++)
                st_async_f32_(peer_hs[r] + doff, hn, peer_mb[r] + moff);
        }

        out[(size_t)t * BH + xbase] = hn;
        if (write_last && t == T_STEPS - 1)
            out[(size_t)T_STEPS * BH + xbase] = hn;
    }
    cluster_sync_();
}

// ---------------- launch ----------------------------------------------------
extern "C" void kernel_launch(void* const* d_in, const int* in_sizes, int n_in,
                              void* d_out, int out_size)
{
    const float* input = (const float*)d_in[0];
    const float* w_in  = (const float*)d_in[1];
    const float* w_rec = (const float*)d_in[2];
    float* out = (float*)d_out;

    int write_last =
        ((size_t)out_size >= (size_t)T_STEPS * BH + (size_t)BH) ? 1 : 0;

    cudaFuncSetAttribute(rnn_scan_kernel,
                         cudaFuncAttributeMaxDynamicSharedMemorySize,
                         SCAN_SMEM_BYTES);

    dim3 grid(HID / XBN, (T_STEPS * BATCH) / XBM);   // (4, 1024)
    xproj_gemm_kernel<<<grid, 256>>>(input, w_in);

    rnn_scan_kernel<<<BATCH / BPC * CLS, 256, SCAN_SMEM_BYTES>>>(
        w_rec, out, write_last);
}